// round 7
// baseline (speedup 1.0000x reference)
#include <cuda_runtime.h>
#include <math.h>

#define B_ 64
#define S_ 512
#define I_ 256
#define H_ 1024
#define O_ 256

// Unified scratch layout [s][b][h]. pre written by GEMM, overwritten in place
// by hidden states during the recurrence.
__device__ float g_buf0[S_ * B_ * H_];
__device__ float g_buf1[S_ * B_ * H_];
// Per-(layer, t, bgroup8, nchunk4) counters; target 64 = 8 producer CTAs x 8
// warps. Monotonic within a launch; zeroed by zero_flags_k each launch.
__device__ int g_flags[2 * S_ * 8 * 4];

typedef unsigned long long u64;

__device__ __forceinline__ u64 pack2(float x, float y) {
    u64 r; asm("mov.b64 %0,{%1,%2};" : "=l"(r) : "f"(x), "f"(y)); return r;
}
__device__ __forceinline__ u64 fma2(u64 a, u64 b, u64 c) {
    u64 d; asm("fma.rn.f32x2 %0,%1,%2,%3;" : "=l"(d) : "l"(a), "l"(b), "l"(c)); return d;
}
__device__ __forceinline__ u64 add2(u64 a, u64 b) {
    u64 d; asm("add.rn.f32x2 %0,%1,%2;" : "=l"(d) : "l"(a), "l"(b)); return d;
}
__device__ __forceinline__ float2 unpk(u64 v) {
    float2 f; asm("mov.b64 {%0,%1},%2;" : "=f"(f.x), "=f"(f.y) : "l"(v)); return f;
}
__device__ __forceinline__ void cpasync16(float* sdst, const float* gsrc) {
    unsigned sa = (unsigned)__cvta_generic_to_shared(sdst);
    asm volatile("cp.async.cg.shared.global [%0], [%1], 16;" :: "r"(sa), "l"(gsrc));
}
__device__ __forceinline__ int ld_acq(const int* p) {
    int v; asm volatile("ld.acquire.gpu.global.b32 %0, [%1];" : "=r"(v) : "l"(p) : "memory");
    return v;
}
__device__ __forceinline__ void red_release(int* p) {
    asm volatile("red.release.gpu.global.add.s32 [%0], 1;" :: "l"(p) : "memory");
}

__global__ void zero_flags_k(int* f) { f[blockIdx.x * 1024 + threadIdx.x] = 0; }

// ---------------------------------------------------------------------------
// Tiled fp32 GEMM, f32x2 microkernel (unchanged).
// ---------------------------------------------------------------------------
template <int K, int AROW, int CROW>
__global__ void __launch_bounds__(128) gemm_k(const float* __restrict__ A,
                                              const float* __restrict__ W,
                                              const float* __restrict__ b1,
                                              const float* __restrict__ b2,
                                              float* __restrict__ C) {
    __shared__ __align__(16) float sA[32][68];
    __shared__ __align__(16) float sB[32][132];

    const int s   = blockIdx.y;
    const int n0  = blockIdx.x * 128;
    const int tid = threadIdx.x;
    const int tm  = tid & 7;
    const int tn  = tid >> 3;

    u64 acc[8][4];
#pragma unroll
    for (int i = 0; i < 8; i++)
#pragma unroll
        for (int j = 0; j < 4; j++) acc[i][j] = 0ull;

    for (int kc = 0; kc < K; kc += 32) {
#pragma unroll
        for (int i = 0; i < 4; i++) {
            int v = tid + i * 128;
            int b = v >> 3, kq = v & 7;
            size_t row = AROW ? ((size_t)s * B_ + b) : ((size_t)b * S_ + s);
            float4 f = __ldg((const float4*)(A + row * K + kc + kq * 4));
            sA[kq * 4 + 0][b] = f.x;
            sA[kq * 4 + 1][b] = f.y;
            sA[kq * 4 + 2][b] = f.z;
            sA[kq * 4 + 3][b] = f.w;
        }
#pragma unroll
        for (int i = 0; i < 8; i++) {
            int v = tid + i * 128;
            int n = v >> 3, kq = v & 7;
            float4 f = __ldg((const float4*)(W + (size_t)(n0 + n) * K + kc + kq * 4));
            sB[kq * 4 + 0][n] = f.x;
            sB[kq * 4 + 1][n] = f.y;
            sB[kq * 4 + 2][n] = f.z;
            sB[kq * 4 + 3][n] = f.w;
        }
        __syncthreads();
#pragma unroll
        for (int k = 0; k < 32; k++) {
            float4 a0 = *(const float4*)&sA[k][tm * 8];
            float4 a1 = *(const float4*)&sA[k][tm * 8 + 4];
            ulonglong2 w01 = *(const ulonglong2*)&sB[k][tn * 8];
            ulonglong2 w23 = *(const ulonglong2*)&sB[k][tn * 8 + 4];
            float av[8] = {a0.x, a0.y, a0.z, a0.w, a1.x, a1.y, a1.z, a1.w};
#pragma unroll
            for (int i = 0; i < 8; i++) {
                u64 ai = pack2(av[i], av[i]);
                acc[i][0] = fma2(ai, w01.x, acc[i][0]);
                acc[i][1] = fma2(ai, w01.y, acc[i][1]);
                acc[i][2] = fma2(ai, w23.x, acc[i][2]);
                acc[i][3] = fma2(ai, w23.y, acc[i][3]);
            }
        }
        __syncthreads();
    }

    float bias[8];
#pragma unroll
    for (int j8 = 0; j8 < 8; j8++) {
        int n = n0 + tn * 8 + j8;
        bias[j8] = b1[n] + (b2 ? b2[n] : 0.0f);
    }

    const int NC = CROW ? O_ : H_;
#pragma unroll
    for (int i = 0; i < 8; i++) {
        int b = tm * 8 + i;
        size_t row = CROW ? ((size_t)b * S_ + s) : ((size_t)s * B_ + b);
        float* Co = C + row * NC + n0 + tn * 8;
        float2 t0 = unpk(acc[i][0]), t1 = unpk(acc[i][1]);
        float2 t2 = unpk(acc[i][2]), t3 = unpk(acc[i][3]);
        *(float4*)Co       = make_float4(t0.x + bias[0], t0.y + bias[1],
                                         t1.x + bias[2], t1.y + bias[3]);
        *(float4*)(Co + 4) = make_float4(t2.x + bias[4], t2.y + bias[5],
                                         t3.x + bias[6], t3.y + bias[7]);
    }
}

// ---------------------------------------------------------------------------
// Recurrence, dual-chain pipelined version.
// grid 128 = 32 n-groups x 4 cta-bgroups. CTA: 32 n x (2 chains of 8 b).
// Chains A = bgroup 2*cbg (rows cbg*16..+8), B = 2*cbg+1 (rows cbg*16+8..+8)
// are INDEPENDENT recurrences; their comm (release->poll->copy) is hidden
// under each other's compute.
// 16 warps: warp = kg*4 + ng4; lane = q*8 + ks. Per-lane tile per chain:
// 2 b x 8 n x 32 k (256 fma2). W slice shared by both chains (128 KB smem).
// ---------------------------------------------------------------------------
#define SW_F   (H_ * 32)         // 32768 floats
#define SHROW  1028
#define SHX_F  (8 * SHROW)       // 8224 floats per chain
#define REDC   544               // u64 per chain: [kg4][b8][17]

__global__ void __launch_bounds__(512) rnn_layer_kernel(const float* __restrict__ Whh,
                                                        float* __restrict__ buf,
                                                        int* __restrict__ flags) {
    extern __shared__ __align__(16) float smem[];
    float* sW    = smem;                       // [k][32] swizzled
    float* sHA   = smem + SW_F;                // [8][1028]
    float* sHB   = sHA + SHX_F;                // [8][1028]
    u64*   redA  = (u64*)(sHB + SHX_F);        // [4][8][17]
    u64*   redB  = redA + REDC;
    float* sPreA = (float*)(redB + REDC);      // [8][32]
    float* sPreB = sPreA + 256;

    const int tid  = threadIdx.x;
    const int warp = tid >> 5, lane = tid & 31;
    const int ng4  = warp & 3;
    const int kg   = warp >> 2;
    const int ks   = lane & 7;
    const int q    = lane >> 3;
    const int cbg  = blockIdx.x & 3;
    const int n0   = (blockIdx.x >> 2) * 32;
    const int bgA  = cbg * 2, bgB = cbg * 2 + 1;
    const int b0A  = cbg * 16, b0B = cbg * 16 + 8;
    const int ca   = (((ng4 * 2) ^ ks) << 2);
    const int cb   = ca ^ 4;
    const int mychunk = n0 >> 8;
    const int gtid = tid & 127;

    // Load W slice with chunk swizzle
#pragma unroll
    for (int i = 0; i < 16; i++) {
        int v = tid + i * 512;
        int j = v >> 8, k4 = v & 255;
        float4 f = __ldg((const float4*)(Whh + (size_t)(n0 + j) * H_ + k4 * 4));
        int sw = (((j >> 2) ^ (k4 & 7)) << 2) + (j & 3);
        sW[(k4 * 4 + 0) * 32 + sw] = f.x;
        sW[(k4 * 4 + 1) * 32 + sw] = f.y;
        sW[(k4 * 4 + 2) * 32 + sw] = f.z;
        sW[(k4 * 4 + 3) * 32 + sw] = f.w;
    }

    // t = 0: h_0 = tanh(pre_0). Warps 0-7: chain A rows; 8-15: chain B rows.
    if (lane < 16) {
        int row = warp & 7;
        int bb  = (warp < 8) ? (b0A + row) : (b0B + row);
        float* addr = buf + (size_t)bb * H_ + n0 + lane * 2;
        float2 v = unpk(*(const u64*)addr);
        *(u64*)addr = pack2(tanhf(v.x), tanhf(v.y));
    }
    __syncwarp();
    if (lane == 0) {
        int bgX = (warp < 8) ? bgA : bgB;
        red_release(&flags[0 * 32 + bgX * 4 + mychunk]);
    }
    __syncthreads();   // sW ready

    const float* hA0 = sHA + q * SHROW + kg * 256 + ks * 4;
    const float* hA1 = sHA + (q + 4) * SHROW + kg * 256 + ks * 4;
    const float* hB0 = sHB + q * SHROW + kg * 256 + ks * 4;
    const float* hB1 = sHB + (q + 4) * SHROW + kg * 256 + ks * 4;
    const float* wbase = sW + (size_t)(kg * 256 + ks * 4) * 32;

#define QUADBAR() asm volatile("bar.sync %0, 128;" :: "r"(1 + kg) : "memory")
#define COMMIT()  asm volatile("cp.async.commit_group;")
#define WAIT1()   asm volatile("cp.async.wait_group 1;" ::: "memory")

    // chunk copy: 8 rows x 256 floats by this quad (4 float4/thread)
#define COPY_CHUNK(SHX, STEP, B0)                                              \
    {                                                                          \
        const float* src_ = buf + ((size_t)(STEP) * B_ + (B0)) * H_ + kg * 256;\
        _Pragma("unroll")                                                      \
        for (int i_ = 0; i_ < 4; i_++) {                                       \
            int v_ = gtid + i_ * 128;                                          \
            int r_ = v_ >> 6, c_ = v_ & 63;                                    \
            cpasync16(&(SHX)[r_ * SHROW + kg * 256 + c_ * 4],                  \
                      src_ + (size_t)r_ * H_ + c_ * 4);                        \
        }                                                                      \
    }
    // pre copy: quad kg handles rows 2kg, 2kg+1 (16 float4, gtid<16)
#define COPY_PRE(SPX, STEP, B0)                                                \
    if (gtid < 16) {                                                           \
        int r_ = kg * 2 + (gtid >> 3), c_ = (gtid & 7) * 4;                    \
        cpasync16(&(SPX)[r_ * 32 + c_],                                        \
                  buf + ((size_t)(STEP) * B_ + (B0) + r_) * H_ + n0 + c_);     \
    }

#define COMPUTE_CHAIN(H0P, H1P, REDX)                                          \
    {                                                                          \
        u64 acc[2][4];                                                         \
        _Pragma("unroll")                                                      \
        for (int i_ = 0; i_ < 2; i_++)                                         \
            _Pragma("unroll")                                                  \
            for (int j_ = 0; j_ < 4; j_++) acc[i_][j_] = 0ull;                 \
        _Pragma("unroll")                                                      \
        for (int it = 0; it < 8; it++) {                                       \
            const int fo = it * 32;                                            \
            float4 h0 = *(const float4*)((H0P) + fo);                          \
            float4 h1 = *(const float4*)((H1P) + fo);                          \
            const float* wr = wbase + (size_t)fo * 32;                         \
            DO_KK(0, x) DO_KK(1, y) DO_KK(2, z) DO_KK(3, w)                    \
        }                                                                      \
        _Pragma("unroll")                                                      \
        for (int i_ = 0; i_ < 2; i_++)                                         \
            _Pragma("unroll")                                                  \
            for (int j_ = 0; j_ < 4; j_++) {                                   \
                u64 a_ = acc[i_][j_];                                          \
                a_ = add2(a_, __shfl_xor_sync(0xffffffffu, a_, 1));            \
                a_ = add2(a_, __shfl_xor_sync(0xffffffffu, a_, 2));            \
                a_ = add2(a_, __shfl_xor_sync(0xffffffffu, a_, 4));            \
                acc[i_][j_] = a_;                                              \
            }                                                                  \
        if (ks == 0) {                                                         \
            _Pragma("unroll")                                                  \
            for (int i_ = 0; i_ < 2; i_++)                                     \
                _Pragma("unroll")                                              \
                for (int j_ = 0; j_ < 4; j_++)                                 \
                    (REDX)[(kg * 8 + (i_ * 4 + q)) * 17 + ng4 * 4 + j_]        \
                        = acc[i_][j_];                                         \
        }                                                                      \
    }

#define DO_KK(KK, CMP)                                                         \
    {                                                                          \
        ulonglong2 wa = *(const ulonglong2*)(wr + KK * 32 + ca);               \
        ulonglong2 wb = *(const ulonglong2*)(wr + KK * 32 + cb);               \
        u64 p0 = pack2(h0.CMP, h0.CMP);                                        \
        u64 p1 = pack2(h1.CMP, h1.CMP);                                        \
        acc[0][0] = fma2(p0, wa.x, acc[0][0]);                                 \
        acc[0][1] = fma2(p0, wa.y, acc[0][1]);                                 \
        acc[0][2] = fma2(p0, wb.x, acc[0][2]);                                 \
        acc[0][3] = fma2(p0, wb.y, acc[0][3]);                                 \
        acc[1][0] = fma2(p1, wa.x, acc[1][0]);                                 \
        acc[1][1] = fma2(p1, wa.y, acc[1][1]);                                 \
        acc[1][2] = fma2(p1, wb.x, acc[1][2]);                                 \
        acc[1][3] = fma2(p1, wb.y, acc[1][3]);                                 \
    }

#define FINALIZE_CHAIN(REDX, SPX, STEP, B0, BGX)                               \
    if (warp < 8) {                                                            \
        if (lane < 16) {                                                       \
            int b_ = warp, P_ = lane;                                          \
            u64 s01 = add2((REDX)[(0 * 8 + b_) * 17 + P_],                     \
                           (REDX)[(1 * 8 + b_) * 17 + P_]);                    \
            u64 s23 = add2((REDX)[(2 * 8 + b_) * 17 + P_],                     \
                           (REDX)[(3 * 8 + b_) * 17 + P_]);                    \
            u64 s_ = add2(s01, s23);                                           \
            s_ = add2(s_, *(const u64*)&(SPX)[b_ * 32 + P_ * 2]);              \
            float2 v_ = unpk(s_);                                              \
            *(u64*)(buf + ((size_t)(STEP) * B_ + (B0) + b_) * H_ + n0 + P_ * 2)\
                = pack2(tanhf(v_.x), tanhf(v_.y));                             \
        }                                                                      \
        __syncwarp();                                                          \
        if (lane == 0)                                                         \
            red_release(&flags[(STEP) * 32 + (BGX) * 4 + mychunk]);            \
    }

    // Prologue: fetch h_A(0) + preA(1)   (group G_A)
    if (gtid == 0) {
        const int* fl = &flags[0 * 32 + bgA * 4 + kg];
        while (ld_acq(fl) < 64) { }
    }
    QUADBAR();
    COPY_CHUNK(sHA, 0, b0A)
    COPY_PRE(sPreA, 1, b0A)
    COMMIT();

    for (int t = 1; t < S_; t++) {
        // ---- phase 1: stage B copy, compute A ----
        if (gtid == 0) {
            const int* fl = &flags[(t - 1) * 32 + bgB * 4 + kg];
            while (ld_acq(fl) < 64) { }
        }
        QUADBAR();
        COPY_CHUNK(sHB, t - 1, b0B)
        COPY_PRE(sPreB, t, b0B)
        COMMIT();               // G_B
        WAIT1();                // G_A (h_A(t-1), preA(t)) done
        QUADBAR();
        COMPUTE_CHAIN(hA0, hA1, redA)
        __syncthreads();
        FINALIZE_CHAIN(redA, sPreA, t, b0A, bgA)

        // ---- phase 2: stage A copy, compute B ----
        if (gtid == 0) {
            const int* fl = &flags[t * 32 + bgA * 4 + kg];
            while (ld_acq(fl) < 64) { }
        }
        QUADBAR();
        COPY_CHUNK(sHA, t, b0A)
        if (t + 1 < S_) COPY_PRE(sPreA, t + 1, b0A)
        COMMIT();               // G_A
        WAIT1();                // G_B done
        QUADBAR();
        COMPUTE_CHAIN(hB0, hB1, redB)
        __syncthreads();
        FINALIZE_CHAIN(redB, sPreB, t, b0B, bgB)
    }
#undef DO_KK
#undef COMPUTE_CHAIN
#undef FINALIZE_CHAIN
#undef COPY_CHUNK
#undef COPY_PRE
#undef QUADBAR
#undef COMMIT
#undef WAIT1
}

// ---------------------------------------------------------------------------

extern "C" void kernel_launch(void* const* d_in, const int* in_sizes, int n_in,
                              void* d_out, int out_size) {
    const float* x      = (const float*)d_in[0];
    const float* W_ih_0 = (const float*)d_in[1];
    const float* W_hh_0 = (const float*)d_in[2];
    const float* b_ih_0 = (const float*)d_in[3];
    const float* b_hh_0 = (const float*)d_in[4];
    const float* W_ih_1 = (const float*)d_in[5];
    const float* W_hh_1 = (const float*)d_in[6];
    const float* b_ih_1 = (const float*)d_in[7];
    const float* b_hh_1 = (const float*)d_in[8];
    const float* fc_w   = (const float*)d_in[9];
    const float* fc_b   = (const float*)d_in[10];
    float* out = (float*)d_out;

    float *buf0, *buf1;
    int* flags;
    cudaGetSymbolAddress((void**)&buf0, g_buf0);
    cudaGetSymbolAddress((void**)&buf1, g_buf1);
    cudaGetSymbolAddress((void**)&flags, g_flags);

    // sW + 2*sH + 2*red + 2*sPre
    const int rnn_smem = SW_F * 4 + 2 * SHX_F * 4 + 2 * REDC * 8 + 2 * 256 * 4; // 207616
    static bool attr_set = false;
    if (!attr_set) {
        cudaFuncSetAttribute(rnn_layer_kernel,
                             cudaFuncAttributeMaxDynamicSharedMemorySize, rnn_smem);
        attr_set = true;
    }

    zero_flags_k<<<32, 1024>>>(flags);
    // 1. pre0[s][b][h] = x @ W_ih_0^T + (b_ih_0 + b_hh_0)
    gemm_k<I_, 0, 0><<<dim3(H_ / 128, S_), 128>>>(x, W_ih_0, b_ih_0, b_hh_0, buf0);
    // 2. layer-0 recurrence (in place)
    rnn_layer_kernel<<<128, 512, rnn_smem>>>(W_hh_0, buf0, flags);
    // 3. pre1[s][b][h] = hs0 @ W_ih_1^T + (b_ih_1 + b_hh_1)
    gemm_k<H_, 1, 0><<<dim3(H_ / 128, S_), 128>>>(buf0, W_ih_1, b_ih_1, b_hh_1, buf1);
    // 4. layer-1 recurrence (in place)
    rnn_layer_kernel<<<128, 512, rnn_smem>>>(W_hh_1, buf1, flags + S_ * 32);
    // 5. out[b][s][o] = hs1 @ fc_w^T + fc_b
    gemm_k<H_, 1, 1><<<dim3(O_ / 128, S_), 128>>>(buf1, fc_w, fc_b, nullptr, out);
}

// round 8
// speedup vs baseline: 1.2548x; 1.2548x over previous
#include <cuda_runtime.h>
#include <math.h>

#define B_ 64
#define S_ 512
#define I_ 256
#define H_ 1024
#define O_ 256

// Unified scratch layout [s][b][h]. pre written by GEMM, overwritten in place
// by hidden states during the recurrence.
__device__ float g_buf0[S_ * B_ * H_];
__device__ float g_buf1[S_ * B_ * H_];
// Chunk-ready flags: [layer][t][bg(4)][chunk(4)], target 8 (one release per
// producer CTA). Monotonic within launch; zeroed each launch.
__device__ int g_flags[2 * S_ * 4 * 4];
// Per-(t, CTA) finalize counters for hierarchical release: [layer][t][cta(128)]
__device__ int g_cnt[2 * S_ * 128];

typedef unsigned long long u64;

__device__ __forceinline__ u64 pack2(float x, float y) {
    u64 r; asm("mov.b64 %0,{%1,%2};" : "=l"(r) : "f"(x), "f"(y)); return r;
}
__device__ __forceinline__ u64 fma2(u64 a, u64 b, u64 c) {
    u64 d; asm("fma.rn.f32x2 %0,%1,%2,%3;" : "=l"(d) : "l"(a), "l"(b), "l"(c)); return d;
}
__device__ __forceinline__ u64 add2(u64 a, u64 b) {
    u64 d; asm("add.rn.f32x2 %0,%1,%2;" : "=l"(d) : "l"(a), "l"(b)); return d;
}
__device__ __forceinline__ float2 unpk(u64 v) {
    float2 f; asm("mov.b64 {%0,%1},%2;" : "=f"(f.x), "=f"(f.y) : "l"(v)); return f;
}
__device__ __forceinline__ void cpasync16(float* sdst, const float* gsrc) {
    unsigned sa = (unsigned)__cvta_generic_to_shared(sdst);
    asm volatile("cp.async.cg.shared.global [%0], [%1], 16;" :: "r"(sa), "l"(gsrc));
}
__device__ __forceinline__ int ld_acq(const int* p) {
    int v; asm volatile("ld.acquire.gpu.global.b32 %0, [%1];" : "=r"(v) : "l"(p) : "memory");
    return v;
}
__device__ __forceinline__ void red_release(int* p) {
    asm volatile("red.release.gpu.global.add.s32 [%0], 1;" :: "l"(p) : "memory");
}
__device__ __forceinline__ int atom_acqrel_add(int* p) {
    int v; asm volatile("atom.acq_rel.gpu.global.add.s32 %0, [%1], 1;"
                        : "=r"(v) : "l"(p) : "memory");
    return v;
}

__global__ void zero_sync_k(int* flags, int nf, int* cnt, int nc) {
    int i = blockIdx.x * 1024 + threadIdx.x;
    if (i < nf) flags[i] = 0;
    if (i < nc) cnt[i] = 0;
}

// ---------------------------------------------------------------------------
// Tiled fp32 GEMM, f32x2 microkernel (unchanged from R6).
// ---------------------------------------------------------------------------
template <int K, int AROW, int CROW>
__global__ void __launch_bounds__(128) gemm_k(const float* __restrict__ A,
                                              const float* __restrict__ W,
                                              const float* __restrict__ b1,
                                              const float* __restrict__ b2,
                                              float* __restrict__ C) {
    __shared__ __align__(16) float sA[32][68];
    __shared__ __align__(16) float sB[32][132];

    const int s   = blockIdx.y;
    const int n0  = blockIdx.x * 128;
    const int tid = threadIdx.x;
    const int tm  = tid & 7;
    const int tn  = tid >> 3;

    u64 acc[8][4];
#pragma unroll
    for (int i = 0; i < 8; i++)
#pragma unroll
        for (int j = 0; j < 4; j++) acc[i][j] = 0ull;

    for (int kc = 0; kc < K; kc += 32) {
#pragma unroll
        for (int i = 0; i < 4; i++) {
            int v = tid + i * 128;
            int b = v >> 3, kq = v & 7;
            size_t row = AROW ? ((size_t)s * B_ + b) : ((size_t)b * S_ + s);
            float4 f = __ldg((const float4*)(A + row * K + kc + kq * 4));
            sA[kq * 4 + 0][b] = f.x;
            sA[kq * 4 + 1][b] = f.y;
            sA[kq * 4 + 2][b] = f.z;
            sA[kq * 4 + 3][b] = f.w;
        }
#pragma unroll
        for (int i = 0; i < 8; i++) {
            int v = tid + i * 128;
            int n = v >> 3, kq = v & 7;
            float4 f = __ldg((const float4*)(W + (size_t)(n0 + n) * K + kc + kq * 4));
            sB[kq * 4 + 0][n] = f.x;
            sB[kq * 4 + 1][n] = f.y;
            sB[kq * 4 + 2][n] = f.z;
            sB[kq * 4 + 3][n] = f.w;
        }
        __syncthreads();
#pragma unroll
        for (int k = 0; k < 32; k++) {
            float4 a0 = *(const float4*)&sA[k][tm * 8];
            float4 a1 = *(const float4*)&sA[k][tm * 8 + 4];
            ulonglong2 w01 = *(const ulonglong2*)&sB[k][tn * 8];
            ulonglong2 w23 = *(const ulonglong2*)&sB[k][tn * 8 + 4];
            float av[8] = {a0.x, a0.y, a0.z, a0.w, a1.x, a1.y, a1.z, a1.w};
#pragma unroll
            for (int i = 0; i < 8; i++) {
                u64 ai = pack2(av[i], av[i]);
                acc[i][0] = fma2(ai, w01.x, acc[i][0]);
                acc[i][1] = fma2(ai, w01.y, acc[i][1]);
                acc[i][2] = fma2(ai, w23.x, acc[i][2]);
                acc[i][3] = fma2(ai, w23.y, acc[i][3]);
            }
        }
        __syncthreads();
    }

    float bias[8];
#pragma unroll
    for (int j8 = 0; j8 < 8; j8++) {
        int n = n0 + tn * 8 + j8;
        bias[j8] = b1[n] + (b2 ? b2[n] : 0.0f);
    }

    const int NC = CROW ? O_ : H_;
#pragma unroll
    for (int i = 0; i < 8; i++) {
        int b = tm * 8 + i;
        size_t row = CROW ? ((size_t)b * S_ + s) : ((size_t)s * B_ + b);
        float* Co = C + row * NC + n0 + tn * 8;
        float2 t0 = unpk(acc[i][0]), t1 = unpk(acc[i][1]);
        float2 t2 = unpk(acc[i][2]), t3 = unpk(acc[i][3]);
        *(float4*)Co       = make_float4(t0.x + bias[0], t0.y + bias[1],
                                         t1.x + bias[2], t1.y + bias[3]);
        *(float4*)(Co + 4) = make_float4(t2.x + bias[4], t2.y + bias[5],
                                         t3.x + bias[6], t3.y + bias[7]);
    }
}

// ---------------------------------------------------------------------------
// Recurrence (R6 skeleton): grid 128 = 32 n-groups x 4 b-groups.
// CTA: 32 n x 16 b. 16 warps: warp = kg*4 + ng4. Lane = q*8 + ks.
// Per-lane tile: 4 b x 8 n x 32 k. sW [k][32] with XOR chunk swizzle.
// NEW in R8:
//  - all threads of a quad poll their chunk flag (per-thread acquire ->
//    cp.async immediately; no poller-wakeup barrier)
//  - hierarchical release: finalize warps atom.acq_rel a per-(t,CTA)
//    counter; the 16th warp does ONE red.release to the chunk flag.
//    Flag target = 8 (one per producer CTA).
// ---------------------------------------------------------------------------
#define SW_F  (H_ * 32)          // 32768 floats (128 KB)
#define SH_ROW 1028              // 1024 + 4 pad
#define SH_F  (16 * SH_ROW)      // 16448 floats
#define RED_U64 1024             // per parity: [kg(4)][b(16)][16]

__global__ void __launch_bounds__(512) rnn_layer_kernel(const float* __restrict__ Whh,
                                                        float* __restrict__ buf,
                                                        int* __restrict__ flags,
                                                        int* __restrict__ cnt) {
    extern __shared__ __align__(16) float smem[];
    float* sW   = smem;                     // [k][32] swizzled
    float* sH   = smem + SW_F;              // [16][1028]
    u64*   red  = (u64*)(sH + SH_F);        // [2][4][16][16]
    float* sPre = (float*)(red + 2 * RED_U64);  // [2][16][32]

    const int tid  = threadIdx.x;
    const int warp = tid >> 5, lane = tid & 31;
    const int ng4  = warp & 3;
    const int kg   = warp >> 2;
    const int ks   = lane & 7;
    const int q    = lane >> 3;
    const int bg   = blockIdx.x & 3;
    const int n0   = (blockIdx.x >> 2) * 32;
    const int b0   = bg * 16;
    const int ca   = (((ng4 * 2) ^ ks) << 2);   // swizzled word offset chunk a
    const int cb   = ca ^ 4;                    // chunk a+1
    const int mychunk = n0 >> 8;
    const int cta  = blockIdx.x;
    const int gtid = tid & 127;                 // id within kg quad

    // Load W slice with chunk swizzle: (k, j) -> sW[k*32 + ((j>>2 ^ k4&7)<<2) + (j&3)]
#pragma unroll
    for (int i = 0; i < 16; i++) {
        int v = tid + i * 512;                  // 0..8191 float4s (j, k4)
        int j = v >> 8, k4 = v & 255;
        float4 f = __ldg((const float4*)(Whh + (size_t)(n0 + j) * H_ + k4 * 4));
        int sw = (((j >> 2) ^ (k4 & 7)) << 2) + (j & 3);
        sW[(k4 * 4 + 0) * 32 + sw] = f.x;
        sW[(k4 * 4 + 1) * 32 + sw] = f.y;
        sW[(k4 * 4 + 2) * 32 + sw] = f.z;
        sW[(k4 * 4 + 3) * 32 + sw] = f.w;
    }

    // t = 0: h_0 = tanh(pre_0); warp = b row, lanes = n-pairs (coalesced)
    if (lane < 16) {
        float* addr = buf + ((size_t)(b0 + warp)) * H_ + n0 + lane * 2;
        float2 v = unpk(*(const u64*)addr);
        *(u64*)addr = pack2(tanhf(v.x), tanhf(v.y));
    }
    __syncwarp();
    if (lane == 0) {
        int old = atom_acqrel_add(&cnt[0 * 128 + cta]);
        if (old == 15) red_release(&flags[(0 * 4 + bg) * 4 + mychunk]);
    }
    __syncthreads();   // sW visible to all before t=1 compute

    // Per-lane h row pointers (b = i*4 + q), k-slice base ks*4 within chunk
    const float* hb0 = sH + (0 * 4 + q) * SH_ROW + kg * 256 + ks * 4;
    const float* hb1 = sH + (1 * 4 + q) * SH_ROW + kg * 256 + ks * 4;
    const float* hb2 = sH + (2 * 4 + q) * SH_ROW + kg * 256 + ks * 4;
    const float* hb3 = sH + (3 * 4 + q) * SH_ROW + kg * 256 + ks * 4;
    const float* wbase = sW + (size_t)(kg * 256 + ks * 4) * 32;

    for (int t = 1; t < S_; t++) {
        u64*   redw = red + (t & 1) * RED_U64;
        float* sPw  = sPre + (t & 1) * 512;

        // Prefetch pre_t tile (own exclusive tile, no dependency)
        if (gtid < 32) {
            int r = kg * 4 + (gtid >> 3), c = (gtid & 7) * 4;
            cpasync16(&sPw[r * 32 + c],
                      buf + ((size_t)t * B_ + b0 + r) * H_ + n0 + c);
        }

        // All threads poll this quad's chunk flag (target 8 producer CTAs);
        // each thread proceeds to its own cp.async as soon as it acquires.
        {
            const int* fl = &flags[((t - 1) * 4 + bg) * 4 + kg];
            while (ld_acq(fl) < 8) { }
        }

        // Copy chunk kg: 16 rows x 256 floats (16 KB), by this quad
        {
            const float* src = buf + ((size_t)(t - 1) * B_ + b0) * H_ + kg * 256;
#pragma unroll
            for (int i = 0; i < 8; i++) {
                int v = gtid + i * 128;          // 0..1023 float4s
                int r = v >> 6, c = v & 63;
                cpasync16(&sH[r * SH_ROW + kg * 256 + c * 4], src + (size_t)r * H_ + c * 4);
            }
            asm volatile("cp.async.wait_all;" ::: "memory");
            asm volatile("bar.sync %0, 128;" :: "r"(1 + kg) : "memory");
        }

        // Compute: 4 b x 8 n x 32 k per lane
        u64 acc[4][4];
#pragma unroll
        for (int i = 0; i < 4; i++)
#pragma unroll
            for (int j = 0; j < 4; j++) acc[i][j] = 0ull;

#pragma unroll
        for (int it = 0; it < 8; it++) {
            const int fo = it * 32;
            float4 h0 = *(const float4*)(hb0 + fo);
            float4 h1 = *(const float4*)(hb1 + fo);
            float4 h2 = *(const float4*)(hb2 + fo);
            float4 h3 = *(const float4*)(hb3 + fo);
            const float* wr = wbase + (size_t)fo * 32;
#define DO_KK(KK, CMP)                                                      \
            {                                                               \
                ulonglong2 wa = *(const ulonglong2*)(wr + KK * 32 + ca);    \
                ulonglong2 wb = *(const ulonglong2*)(wr + KK * 32 + cb);    \
                u64 p0 = pack2(h0.CMP, h0.CMP);                             \
                u64 p1 = pack2(h1.CMP, h1.CMP);                             \
                u64 p2 = pack2(h2.CMP, h2.CMP);                             \
                u64 p3 = pack2(h3.CMP, h3.CMP);                             \
                acc[0][0] = fma2(p0, wa.x, acc[0][0]);                      \
                acc[0][1] = fma2(p0, wa.y, acc[0][1]);                      \
                acc[0][2] = fma2(p0, wb.x, acc[0][2]);                      \
                acc[0][3] = fma2(p0, wb.y, acc[0][3]);                      \
                acc[1][0] = fma2(p1, wa.x, acc[1][0]);                      \
                acc[1][1] = fma2(p1, wa.y, acc[1][1]);                      \
                acc[1][2] = fma2(p1, wb.x, acc[1][2]);                      \
                acc[1][3] = fma2(p1, wb.y, acc[1][3]);                      \
                acc[2][0] = fma2(p2, wa.x, acc[2][0]);                      \
                acc[2][1] = fma2(p2, wa.y, acc[2][1]);                      \
                acc[2][2] = fma2(p2, wb.x, acc[2][2]);                      \
                acc[2][3] = fma2(p2, wb.y, acc[2][3]);                      \
                acc[3][0] = fma2(p3, wa.x, acc[3][0]);                      \
                acc[3][1] = fma2(p3, wa.y, acc[3][1]);                      \
                acc[3][2] = fma2(p3, wb.x, acc[3][2]);                      \
                acc[3][3] = fma2(p3, wb.y, acc[3][3]);                      \
            }
            DO_KK(0, x)
            DO_KK(1, y)
            DO_KK(2, z)
            DO_KK(3, w)
#undef DO_KK
        }

        // Fold 8 k-slices (lane bits 0..2)
#pragma unroll
        for (int i = 0; i < 4; i++)
#pragma unroll
            for (int j = 0; j < 4; j++) {
                acc[i][j] = add2(acc[i][j], __shfl_xor_sync(0xffffffffu, acc[i][j], 1));
                acc[i][j] = add2(acc[i][j], __shfl_xor_sync(0xffffffffu, acc[i][j], 2));
                acc[i][j] = add2(acc[i][j], __shfl_xor_sync(0xffffffffu, acc[i][j], 4));
            }

        if (ks == 0) {
#pragma unroll
            for (int i = 0; i < 4; i++)
#pragma unroll
                for (int j = 0; j < 4; j++)
                    redw[(kg * 16 + (i * 4 + q)) * 16 + ng4 * 4 + j] = acc[i][j];
        }
        __syncthreads();

        // Finalize: warp = b row, lanes 0..15 = n-pairs; coalesced store.
        if (lane < 16) {
            int b = warp, P = lane;
            u64 s01 = add2(redw[(0 * 16 + b) * 16 + P], redw[(1 * 16 + b) * 16 + P]);
            u64 s23 = add2(redw[(2 * 16 + b) * 16 + P], redw[(3 * 16 + b) * 16 + P]);
            u64 s = add2(s01, s23);
            s = add2(s, *(const u64*)&sPw[b * 32 + P * 2]);
            float2 v = unpk(s);
            *(u64*)(buf + ((size_t)t * B_ + b0 + b) * H_ + n0 + P * 2)
                = pack2(tanhf(v.x), tanhf(v.y));
        }
        __syncwarp();
        // Hierarchical release: 16 warps bump the per-(t,CTA) counter
        // (distinct address per CTA -> no hot-spot); 16th releases the flag.
        if (lane == 0) {
            int old = atom_acqrel_add(&cnt[t * 128 + cta]);
            if (old == 15) red_release(&flags[(t * 4 + bg) * 4 + mychunk]);
        }
    }
}

// ---------------------------------------------------------------------------

extern "C" void kernel_launch(void* const* d_in, const int* in_sizes, int n_in,
                              void* d_out, int out_size) {
    const float* x      = (const float*)d_in[0];
    const float* W_ih_0 = (const float*)d_in[1];
    const float* W_hh_0 = (const float*)d_in[2];
    const float* b_ih_0 = (const float*)d_in[3];
    const float* b_hh_0 = (const float*)d_in[4];
    const float* W_ih_1 = (const float*)d_in[5];
    const float* W_hh_1 = (const float*)d_in[6];
    const float* b_ih_1 = (const float*)d_in[7];
    const float* b_hh_1 = (const float*)d_in[8];
    const float* fc_w   = (const float*)d_in[9];
    const float* fc_b   = (const float*)d_in[10];
    float* out = (float*)d_out;

    float *buf0, *buf1;
    int *flags, *cnt;
    cudaGetSymbolAddress((void**)&buf0, g_buf0);
    cudaGetSymbolAddress((void**)&buf1, g_buf1);
    cudaGetSymbolAddress((void**)&flags, g_flags);
    cudaGetSymbolAddress((void**)&cnt, g_cnt);

    const int rnn_smem = (SW_F + SH_F) * 4 + 2 * RED_U64 * 8 + 2 * 512 * 4;  // 217344 B
    static bool attr_set = false;
    if (!attr_set) {
        cudaFuncSetAttribute(rnn_layer_kernel,
                             cudaFuncAttributeMaxDynamicSharedMemorySize, rnn_smem);
        attr_set = true;
    }

    const int NF = 2 * S_ * 16;     // 16384
    const int NC = 2 * S_ * 128;    // 131072
    zero_sync_k<<<(NC + 1023) / 1024, 1024>>>(flags, NF, cnt, NC);
    // 1. pre0[s][b][h] = x @ W_ih_0^T + (b_ih_0 + b_hh_0)
    gemm_k<I_, 0, 0><<<dim3(H_ / 128, S_), 128>>>(x, W_ih_0, b_ih_0, b_hh_0, buf0);
    // 2. layer-0 recurrence (in place)
    rnn_layer_kernel<<<128, 512, rnn_smem>>>(W_hh_0, buf0, flags, cnt);
    // 3. pre1[s][b][h] = hs0 @ W_ih_1^T + (b_ih_1 + b_hh_1)
    gemm_k<H_, 1, 0><<<dim3(H_ / 128, S_), 128>>>(buf0, W_ih_1, b_ih_1, b_hh_1, buf1);
    // 4. layer-1 recurrence (in place)
    rnn_layer_kernel<<<128, 512, rnn_smem>>>(W_hh_1, buf1, flags + S_ * 16, cnt + S_ * 128);
    // 5. out[b][s][o] = hs1 @ fc_w^T + fc_b
    gemm_k<H_, 1, 1><<<dim3(O_ / 128, S_), 128>>>(buf1, fc_w, fc_b, nullptr, out);
}

// round 9
// speedup vs baseline: 1.2608x; 1.0048x over previous
#include <cuda_runtime.h>
#include <math.h>

#define B_ 64
#define S_ 512
#define I_ 256
#define H_ 1024
#define O_ 256

// Unified scratch layout [s][b][h]. pre written by GEMM, overwritten in place
// by hidden states during the recurrence.
__device__ float g_buf0[S_ * B_ * H_];
__device__ float g_buf1[S_ * B_ * H_];
// Chunk-ready flags: [layer][t][bg(4)][chunk(4)], target 8 (one release per
// producer CTA). Monotonic within launch; zeroed each launch.
__device__ int g_flags[2 * S_ * 4 * 4];
// Per-(t, CTA) finalize counters for hierarchical release: [layer][t][cta(128)]
__device__ int g_cnt[2 * S_ * 128];

typedef unsigned long long u64;

__device__ __forceinline__ u64 pack2(float x, float y) {
    u64 r; asm("mov.b64 %0,{%1,%2};" : "=l"(r) : "f"(x), "f"(y)); return r;
}
__device__ __forceinline__ u64 fma2(u64 a, u64 b, u64 c) {
    u64 d; asm("fma.rn.f32x2 %0,%1,%2,%3;" : "=l"(d) : "l"(a), "l"(b), "l"(c)); return d;
}
__device__ __forceinline__ u64 add2(u64 a, u64 b) {
    u64 d; asm("add.rn.f32x2 %0,%1,%2;" : "=l"(d) : "l"(a), "l"(b)); return d;
}
__device__ __forceinline__ float2 unpk(u64 v) {
    float2 f; asm("mov.b64 {%0,%1},%2;" : "=f"(f.x), "=f"(f.y) : "l"(v)); return f;
}
__device__ __forceinline__ void cpasync16(float* sdst, const float* gsrc) {
    unsigned sa = (unsigned)__cvta_generic_to_shared(sdst);
    asm volatile("cp.async.cg.shared.global [%0], [%1], 16;" :: "r"(sa), "l"(gsrc));
}
__device__ __forceinline__ int ld_acq(const int* p) {
    int v; asm volatile("ld.acquire.gpu.global.b32 %0, [%1];" : "=r"(v) : "l"(p) : "memory");
    return v;
}
__device__ __forceinline__ void red_release(int* p) {
    asm volatile("red.release.gpu.global.add.s32 [%0], 1;" :: "l"(p) : "memory");
}
__device__ __forceinline__ int atom_acqrel_add(int* p) {
    int v; asm volatile("atom.acq_rel.gpu.global.add.s32 %0, [%1], 1;"
                        : "=r"(v) : "l"(p) : "memory");
    return v;
}

__global__ void zero_sync_k(int* flags, int nf, int* cnt, int nc) {
    int i = blockIdx.x * 1024 + threadIdx.x;
    if (i < nf) flags[i] = 0;
    if (i < nc) cnt[i] = 0;
}

// ---------------------------------------------------------------------------
// Tiled fp32 GEMM, f32x2 microkernel (unchanged from R6).
// ---------------------------------------------------------------------------
template <int K, int AROW, int CROW>
__global__ void __launch_bounds__(128) gemm_k(const float* __restrict__ A,
                                              const float* __restrict__ W,
                                              const float* __restrict__ b1,
                                              const float* __restrict__ b2,
                                              float* __restrict__ C) {
    __shared__ __align__(16) float sA[32][68];
    __shared__ __align__(16) float sB[32][132];

    const int s   = blockIdx.y;
    const int n0  = blockIdx.x * 128;
    const int tid = threadIdx.x;
    const int tm  = tid & 7;
    const int tn  = tid >> 3;

    u64 acc[8][4];
#pragma unroll
    for (int i = 0; i < 8; i++)
#pragma unroll
        for (int j = 0; j < 4; j++) acc[i][j] = 0ull;

    for (int kc = 0; kc < K; kc += 32) {
#pragma unroll
        for (int i = 0; i < 4; i++) {
            int v = tid + i * 128;
            int b = v >> 3, kq = v & 7;
            size_t row = AROW ? ((size_t)s * B_ + b) : ((size_t)b * S_ + s);
            float4 f = __ldg((const float4*)(A + row * K + kc + kq * 4));
            sA[kq * 4 + 0][b] = f.x;
            sA[kq * 4 + 1][b] = f.y;
            sA[kq * 4 + 2][b] = f.z;
            sA[kq * 4 + 3][b] = f.w;
        }
#pragma unroll
        for (int i = 0; i < 8; i++) {
            int v = tid + i * 128;
            int n = v >> 3, kq = v & 7;
            float4 f = __ldg((const float4*)(W + (size_t)(n0 + n) * K + kc + kq * 4));
            sB[kq * 4 + 0][n] = f.x;
            sB[kq * 4 + 1][n] = f.y;
            sB[kq * 4 + 2][n] = f.z;
            sB[kq * 4 + 3][n] = f.w;
        }
        __syncthreads();
#pragma unroll
        for (int k = 0; k < 32; k++) {
            float4 a0 = *(const float4*)&sA[k][tm * 8];
            float4 a1 = *(const float4*)&sA[k][tm * 8 + 4];
            ulonglong2 w01 = *(const ulonglong2*)&sB[k][tn * 8];
            ulonglong2 w23 = *(const ulonglong2*)&sB[k][tn * 8 + 4];
            float av[8] = {a0.x, a0.y, a0.z, a0.w, a1.x, a1.y, a1.z, a1.w};
#pragma unroll
            for (int i = 0; i < 8; i++) {
                u64 ai = pack2(av[i], av[i]);
                acc[i][0] = fma2(ai, w01.x, acc[i][0]);
                acc[i][1] = fma2(ai, w01.y, acc[i][1]);
                acc[i][2] = fma2(ai, w23.x, acc[i][2]);
                acc[i][3] = fma2(ai, w23.y, acc[i][3]);
            }
        }
        __syncthreads();
    }

    float bias[8];
#pragma unroll
    for (int j8 = 0; j8 < 8; j8++) {
        int n = n0 + tn * 8 + j8;
        bias[j8] = b1[n] + (b2 ? b2[n] : 0.0f);
    }

    const int NC = CROW ? O_ : H_;
#pragma unroll
    for (int i = 0; i < 8; i++) {
        int b = tm * 8 + i;
        size_t row = CROW ? ((size_t)b * S_ + s) : ((size_t)s * B_ + b);
        float* Co = C + row * NC + n0 + tn * 8;
        float2 t0 = unpk(acc[i][0]), t1 = unpk(acc[i][1]);
        float2 t2 = unpk(acc[i][2]), t3 = unpk(acc[i][3]);
        *(float4*)Co       = make_float4(t0.x + bias[0], t0.y + bias[1],
                                         t1.x + bias[2], t1.y + bias[3]);
        *(float4*)(Co + 4) = make_float4(t2.x + bias[4], t2.y + bias[5],
                                         t3.x + bias[6], t3.y + bias[7]);
    }
}

// ---------------------------------------------------------------------------
// Recurrence (R6 skeleton): grid 128 = 32 n-groups x 4 b-groups.
// CTA: 32 n x 16 b. 16 warps: warp = kg*4 + ng4. Lane = q*8 + ks.
// Per-lane tile: 4 b x 8 n x 32 k. sW [k][32] with XOR chunk swizzle.
// NEW in R8:
//  - all threads of a quad poll their chunk flag (per-thread acquire ->
//    cp.async immediately; no poller-wakeup barrier)
//  - hierarchical release: finalize warps atom.acq_rel a per-(t,CTA)
//    counter; the 16th warp does ONE red.release to the chunk flag.
//    Flag target = 8 (one per producer CTA).
// ---------------------------------------------------------------------------
#define SW_F  (H_ * 32)          // 32768 floats (128 KB)
#define SH_ROW 1028              // 1024 + 4 pad
#define SH_F  (16 * SH_ROW)      // 16448 floats
#define RED_U64 1024             // per parity: [kg(4)][b(16)][16]

__global__ void __launch_bounds__(512) rnn_layer_kernel(const float* __restrict__ Whh,
                                                        float* __restrict__ buf,
                                                        int* __restrict__ flags,
                                                        int* __restrict__ cnt) {
    extern __shared__ __align__(16) float smem[];
    float* sW   = smem;                     // [k][32] swizzled
    float* sH   = smem + SW_F;              // [16][1028]
    u64*   red  = (u64*)(sH + SH_F);        // [2][4][16][16]
    float* sPre = (float*)(red + 2 * RED_U64);  // [2][16][32]

    const int tid  = threadIdx.x;
    const int warp = tid >> 5, lane = tid & 31;
    const int ng4  = warp & 3;
    const int kg   = warp >> 2;
    const int ks   = lane & 7;
    const int q    = lane >> 3;
    const int bg   = blockIdx.x & 3;
    const int n0   = (blockIdx.x >> 2) * 32;
    const int b0   = bg * 16;
    const int ca   = (((ng4 * 2) ^ ks) << 2);   // swizzled word offset chunk a
    const int cb   = ca ^ 4;                    // chunk a+1
    const int mychunk = n0 >> 8;
    const int cta  = blockIdx.x;
    const int gtid = tid & 127;                 // id within kg quad

    // Load W slice with chunk swizzle: (k, j) -> sW[k*32 + ((j>>2 ^ k4&7)<<2) + (j&3)]
#pragma unroll
    for (int i = 0; i < 16; i++) {
        int v = tid + i * 512;                  // 0..8191 float4s (j, k4)
        int j = v >> 8, k4 = v & 255;
        float4 f = __ldg((const float4*)(Whh + (size_t)(n0 + j) * H_ + k4 * 4));
        int sw = (((j >> 2) ^ (k4 & 7)) << 2) + (j & 3);
        sW[(k4 * 4 + 0) * 32 + sw] = f.x;
        sW[(k4 * 4 + 1) * 32 + sw] = f.y;
        sW[(k4 * 4 + 2) * 32 + sw] = f.z;
        sW[(k4 * 4 + 3) * 32 + sw] = f.w;
    }

    // t = 0: h_0 = tanh(pre_0); warp = b row, lanes = n-pairs (coalesced)
    if (lane < 16) {
        float* addr = buf + ((size_t)(b0 + warp)) * H_ + n0 + lane * 2;
        float2 v = unpk(*(const u64*)addr);
        *(u64*)addr = pack2(tanhf(v.x), tanhf(v.y));
    }
    __syncwarp();
    if (lane == 0) {
        int old = atom_acqrel_add(&cnt[0 * 128 + cta]);
        if (old == 15) red_release(&flags[(0 * 4 + bg) * 4 + mychunk]);
    }
    __syncthreads();   // sW visible to all before t=1 compute

    // Per-lane h row pointers (b = i*4 + q), k-slice base ks*4 within chunk
    const float* hb0 = sH + (0 * 4 + q) * SH_ROW + kg * 256 + ks * 4;
    const float* hb1 = sH + (1 * 4 + q) * SH_ROW + kg * 256 + ks * 4;
    const float* hb2 = sH + (2 * 4 + q) * SH_ROW + kg * 256 + ks * 4;
    const float* hb3 = sH + (3 * 4 + q) * SH_ROW + kg * 256 + ks * 4;
    const float* wbase = sW + (size_t)(kg * 256 + ks * 4) * 32;

    for (int t = 1; t < S_; t++) {
        u64*   redw = red + (t & 1) * RED_U64;
        float* sPw  = sPre + (t & 1) * 512;

        // Prefetch pre_t tile (own exclusive tile, no dependency)
        if (gtid < 32) {
            int r = kg * 4 + (gtid >> 3), c = (gtid & 7) * 4;
            cpasync16(&sPw[r * 32 + c],
                      buf + ((size_t)t * B_ + b0 + r) * H_ + n0 + c);
        }

        // All threads poll this quad's chunk flag (target 8 producer CTAs);
        // each thread proceeds to its own cp.async as soon as it acquires.
        {
            const int* fl = &flags[((t - 1) * 4 + bg) * 4 + kg];
            while (ld_acq(fl) < 8) { }
        }

        // Copy chunk kg: 16 rows x 256 floats (16 KB), by this quad
        {
            const float* src = buf + ((size_t)(t - 1) * B_ + b0) * H_ + kg * 256;
#pragma unroll
            for (int i = 0; i < 8; i++) {
                int v = gtid + i * 128;          // 0..1023 float4s
                int r = v >> 6, c = v & 63;
                cpasync16(&sH[r * SH_ROW + kg * 256 + c * 4], src + (size_t)r * H_ + c * 4);
            }
            asm volatile("cp.async.wait_all;" ::: "memory");
            asm volatile("bar.sync %0, 128;" :: "r"(1 + kg) : "memory");
        }

        // Compute: 4 b x 8 n x 32 k per lane
        u64 acc[4][4];
#pragma unroll
        for (int i = 0; i < 4; i++)
#pragma unroll
            for (int j = 0; j < 4; j++) acc[i][j] = 0ull;

#pragma unroll
        for (int it = 0; it < 8; it++) {
            const int fo = it * 32;
            float4 h0 = *(const float4*)(hb0 + fo);
            float4 h1 = *(const float4*)(hb1 + fo);
            float4 h2 = *(const float4*)(hb2 + fo);
            float4 h3 = *(const float4*)(hb3 + fo);
            const float* wr = wbase + (size_t)fo * 32;
#define DO_KK(KK, CMP)                                                      \
            {                                                               \
                ulonglong2 wa = *(const ulonglong2*)(wr + KK * 32 + ca);    \
                ulonglong2 wb = *(const ulonglong2*)(wr + KK * 32 + cb);    \
                u64 p0 = pack2(h0.CMP, h0.CMP);                             \
                u64 p1 = pack2(h1.CMP, h1.CMP);                             \
                u64 p2 = pack2(h2.CMP, h2.CMP);                             \
                u64 p3 = pack2(h3.CMP, h3.CMP);                             \
                acc[0][0] = fma2(p0, wa.x, acc[0][0]);                      \
                acc[0][1] = fma2(p0, wa.y, acc[0][1]);                      \
                acc[0][2] = fma2(p0, wb.x, acc[0][2]);                      \
                acc[0][3] = fma2(p0, wb.y, acc[0][3]);                      \
                acc[1][0] = fma2(p1, wa.x, acc[1][0]);                      \
                acc[1][1] = fma2(p1, wa.y, acc[1][1]);                      \
                acc[1][2] = fma2(p1, wb.x, acc[1][2]);                      \
                acc[1][3] = fma2(p1, wb.y, acc[1][3]);                      \
                acc[2][0] = fma2(p2, wa.x, acc[2][0]);                      \
                acc[2][1] = fma2(p2, wa.y, acc[2][1]);                      \
                acc[2][2] = fma2(p2, wb.x, acc[2][2]);                      \
                acc[2][3] = fma2(p2, wb.y, acc[2][3]);                      \
                acc[3][0] = fma2(p3, wa.x, acc[3][0]);                      \
                acc[3][1] = fma2(p3, wa.y, acc[3][1]);                      \
                acc[3][2] = fma2(p3, wb.x, acc[3][2]);                      \
                acc[3][3] = fma2(p3, wb.y, acc[3][3]);                      \
            }
            DO_KK(0, x)
            DO_KK(1, y)
            DO_KK(2, z)
            DO_KK(3, w)
#undef DO_KK
        }

        // Fold 8 k-slices (lane bits 0..2)
#pragma unroll
        for (int i = 0; i < 4; i++)
#pragma unroll
            for (int j = 0; j < 4; j++) {
                acc[i][j] = add2(acc[i][j], __shfl_xor_sync(0xffffffffu, acc[i][j], 1));
                acc[i][j] = add2(acc[i][j], __shfl_xor_sync(0xffffffffu, acc[i][j], 2));
                acc[i][j] = add2(acc[i][j], __shfl_xor_sync(0xffffffffu, acc[i][j], 4));
            }

        if (ks == 0) {
#pragma unroll
            for (int i = 0; i < 4; i++)
#pragma unroll
                for (int j = 0; j < 4; j++)
                    redw[(kg * 16 + (i * 4 + q)) * 16 + ng4 * 4 + j] = acc[i][j];
        }
        __syncthreads();

        // Finalize: warp = b row, lanes 0..15 = n-pairs; coalesced store.
        if (lane < 16) {
            int b = warp, P = lane;
            u64 s01 = add2(redw[(0 * 16 + b) * 16 + P], redw[(1 * 16 + b) * 16 + P]);
            u64 s23 = add2(redw[(2 * 16 + b) * 16 + P], redw[(3 * 16 + b) * 16 + P]);
            u64 s = add2(s01, s23);
            s = add2(s, *(const u64*)&sPw[b * 32 + P * 2]);
            float2 v = unpk(s);
            *(u64*)(buf + ((size_t)t * B_ + b0 + b) * H_ + n0 + P * 2)
                = pack2(tanhf(v.x), tanhf(v.y));
        }
        __syncwarp();
        // Hierarchical release: 16 warps bump the per-(t,CTA) counter
        // (distinct address per CTA -> no hot-spot); 16th releases the flag.
        if (lane == 0) {
            int old = atom_acqrel_add(&cnt[t * 128 + cta]);
            if (old == 15) red_release(&flags[(t * 4 + bg) * 4 + mychunk]);
        }
    }
}

// ---------------------------------------------------------------------------

extern "C" void kernel_launch(void* const* d_in, const int* in_sizes, int n_in,
                              void* d_out, int out_size) {
    const float* x      = (const float*)d_in[0];
    const float* W_ih_0 = (const float*)d_in[1];
    const float* W_hh_0 = (const float*)d_in[2];
    const float* b_ih_0 = (const float*)d_in[3];
    const float* b_hh_0 = (const float*)d_in[4];
    const float* W_ih_1 = (const float*)d_in[5];
    const float* W_hh_1 = (const float*)d_in[6];
    const float* b_ih_1 = (const float*)d_in[7];
    const float* b_hh_1 = (const float*)d_in[8];
    const float* fc_w   = (const float*)d_in[9];
    const float* fc_b   = (const float*)d_in[10];
    float* out = (float*)d_out;

    float *buf0, *buf1;
    int *flags, *cnt;
    cudaGetSymbolAddress((void**)&buf0, g_buf0);
    cudaGetSymbolAddress((void**)&buf1, g_buf1);
    cudaGetSymbolAddress((void**)&flags, g_flags);
    cudaGetSymbolAddress((void**)&cnt, g_cnt);

    const int rnn_smem = (SW_F + SH_F) * 4 + 2 * RED_U64 * 8 + 2 * 512 * 4;  // 217344 B
    static bool attr_set = false;
    if (!attr_set) {
        cudaFuncSetAttribute(rnn_layer_kernel,
                             cudaFuncAttributeMaxDynamicSharedMemorySize, rnn_smem);
        attr_set = true;
    }

    const int NF = 2 * S_ * 16;     // 16384
    const int NC = 2 * S_ * 128;    // 131072
    zero_sync_k<<<(NC + 1023) / 1024, 1024>>>(flags, NF, cnt, NC);
    // 1. pre0[s][b][h] = x @ W_ih_0^T + (b_ih_0 + b_hh_0)
    gemm_k<I_, 0, 0><<<dim3(H_ / 128, S_), 128>>>(x, W_ih_0, b_ih_0, b_hh_0, buf0);
    // 2. layer-0 recurrence (in place)
    rnn_layer_kernel<<<128, 512, rnn_smem>>>(W_hh_0, buf0, flags, cnt);
    // 3. pre1[s][b][h] = hs0 @ W_ih_1^T + (b_ih_1 + b_hh_1)
    gemm_k<H_, 1, 0><<<dim3(H_ / 128, S_), 128>>>(buf0, W_ih_1, b_ih_1, b_hh_1, buf1);
    // 4. layer-1 recurrence (in place)
    rnn_layer_kernel<<<128, 512, rnn_smem>>>(W_hh_1, buf1, flags + S_ * 16, cnt + S_ * 128);
    // 5. out[b][s][o] = hs1 @ fc_w^T + fc_b
    gemm_k<H_, 1, 1><<<dim3(O_ / 128, S_), 128>>>(buf1, fc_w, fc_b, nullptr, out);
}